// round 6
// baseline (speedup 1.0000x reference)
#include <cuda_runtime.h>
#include <cstdint>

typedef unsigned long long ull;

#define TPB   512
#define NB    2
#define R_    16
#define D_    1024

// ---- packed f32x2 helpers ----
__device__ __forceinline__ ull ffma2(ull a, ull b, ull c) {
    ull d;
    asm("fma.rn.f32x2 %0, %1, %2, %3;" : "=l"(d) : "l"(a), "l"(b), "l"(c));
    return d;
}
__device__ __forceinline__ ull fmul2(ull a, ull b) {
    ull d;
    asm("mul.rn.f32x2 %0, %1, %2;" : "=l"(d) : "l"(a), "l"(b));
    return d;
}
__device__ __forceinline__ ull fadd2(ull a, ull b) {
    ull d;
    asm("add.rn.f32x2 %0, %1, %2;" : "=l"(d) : "l"(a), "l"(b));
    return d;
}
__device__ __forceinline__ float lo_(ull v) { return __int_as_float((int)(unsigned)(v & 0xffffffffull)); }
__device__ __forceinline__ float hi_(ull v) { return __int_as_float((int)(unsigned)(v >> 32)); }
__device__ __forceinline__ ull   dup_(float v) { unsigned u = __float_as_uint(v); return ((ull)u << 32) | (ull)u; }
__device__ __forceinline__ ull ldg64(const void* p) {
    ull v;
    asm("ld.global.nc.u64 %0, [%1];" : "=l"(v) : "l"(p));
    return v;
}

__global__ __launch_bounds__(TPB, 2)
void rlora_kernel(const int*   __restrict__ indices,
                  const float* __restrict__ baseW,
                  const float* __restrict__ loraA,
                  const float* __restrict__ loraB,
                  float*       __restrict__ out,
                  int n_rows, int nbatch)
{
    // planar partial arrays: conflict-free STS.32, LDS.128-friendly reduce
    __shared__ float red0[NB][TPB];   // x2 partials
    __shared__ float red1[NB][TPB];   // y2 partials
    __shared__ float red2[NB][TPB];   // xy partials
    __shared__ ull   sb[2][NB][R_];   // 0.1*loraB rows, dup'd halves
    __shared__ int   sidx[2][NB];
    __shared__ ull   scx[NB], scy[NB];

    const int tid  = threadIdx.x;
    const int wid  = tid >> 5;
    const int lane = tid & 31;
    const int d0   = tid * 2;         // this lane owns columns d0, d0+1

    // lora_A register-resident: a[r] = A[r][d0:d0+2]  (32 regs)
    ull a[R_];
    #pragma unroll
    for (int r = 0; r < R_; ++r)
        a[r] = ldg64(loraA + r * D_ + d0);

    const int S    = gridDim.x;
    const int b0   = blockIdx.x;
    const int kmax = (nbatch - b0 + S - 1) / S;

    // ---------------- prologue ----------------
    ull xc[NB];
    {
        #pragma unroll
        for (int row = 0; row < NB; ++row) {
            int g = b0 * NB + row;
            if (g < n_rows) {
                int idx = __ldg(indices + g);
                xc[row] = ldg64(baseW + (size_t)idx * D_ + d0);
            } else xc[row] = 0ull;
        }
        if (tid < NB) {   // batch 1 indices -> slot 1
            int g = (b0 + S) * NB + tid;
            sidx[1][tid] = ((b0 + S) < nbatch && g < n_rows) ? __ldg(indices + g) : -1;
        }
        if (tid < NB * R_) {   // batch 0 b-rows -> sb slot 0
            int row = tid >> 4, r = tid & 15;
            int g = b0 * NB + row;
            sb[0][row][r] = (g < n_rows)
                ? dup_(0.1f * __ldg(loraB + (size_t)__ldg(indices + g) * R_ + r)) : 0ull;
        }
    }
    __syncthreads();

    for (int k = 0; k < kmax; ++k) {
        const int  p        = k & 1;
        const bool havenext = (k + 1) < kmax;

        // ---- prefetch x(k+1) into registers (batch m lives in sidx[m&1]) ----
        ull xn[NB];
        #pragma unroll
        for (int row = 0; row < NB; ++row) {
            int idx = havenext ? sidx[(k + 1) & 1][row] : -1;
            xn[row] = (idx >= 0) ? ldg64(baseW + (size_t)idx * D_ + d0) : 0ull;
        }
        // ---- stage sidx(batch k+2) -> slot k&1 ; sb(batch k+1) -> slot (k+1)&1 ----
        if (tid < NB) {
            long long g = (long long)(b0 + (k + 2) * S) * NB + tid;
            sidx[p][tid] = ((k + 2) < kmax && g < n_rows) ? __ldg(indices + g) : -1;
        }
        if (tid < NB * R_) {
            int row = tid >> 4, r = tid & 15;
            int idx = havenext ? sidx[(k + 1) & 1][row] : -1;
            sb[(k + 1) & 1][row][r] = (idx >= 0)
                ? dup_(0.1f * __ldg(loraB + (size_t)idx * R_ + r)) : 0ull;
        }

        // ---- delta + raw partials (no shuffles) ----
        ull dv[NB];
        #pragma unroll
        for (int row = 0; row < NB; ++row) {
            const ulonglong2* bp = reinterpret_cast<const ulonglong2*>(sb[p][row]);
            ulonglong2 b01 = bp[0];
            ull acc0 = fmul2(b01.x, a[0]);
            ull acc1 = fmul2(b01.y, a[1]);
            #pragma unroll
            for (int kk = 1; kk < R_ / 2; ++kk) {
                ulonglong2 b = bp[kk];
                acc0 = ffma2(b.x, a[2 * kk],     acc0);
                acc1 = ffma2(b.y, a[2 * kk + 1], acc1);
            }
            ull dvv = fadd2(acc0, acc1);
            dv[row] = dvv;

            float xl = lo_(xc[row]), xh = hi_(xc[row]);
            float yl = lo_(dvv),     yh = hi_(dvv);
            red0[row][tid] = fmaf(xl, xl, xh * xh);
            red1[row][tid] = fmaf(yl, yl, yh * yh);
            red2[row][tid] = fmaf(xl, yl, xh * yh);
        }
        __syncthreads();

        // ---- warp w (< NB) reduces row w over 512 partials + epilogue ----
        if (wid < NB) {
            // each planar array: 512 floats = 128 ulonglong2; 4 per lane
            float s0, s1, s2;
            {
                const ulonglong2* q = reinterpret_cast<const ulonglong2*>(red0[wid]);
                ulonglong2 v0 = q[lane], v1 = q[lane + 32], v2 = q[lane + 64], v3 = q[lane + 96];
                ull t = fadd2(fadd2(fadd2(v0.x, v0.y), fadd2(v1.x, v1.y)),
                              fadd2(fadd2(v2.x, v2.y), fadd2(v3.x, v3.y)));
                s0 = lo_(t) + hi_(t);
            }
            {
                const ulonglong2* q = reinterpret_cast<const ulonglong2*>(red1[wid]);
                ulonglong2 v0 = q[lane], v1 = q[lane + 32], v2 = q[lane + 64], v3 = q[lane + 96];
                ull t = fadd2(fadd2(fadd2(v0.x, v0.y), fadd2(v1.x, v1.y)),
                              fadd2(fadd2(v2.x, v2.y), fadd2(v3.x, v3.y)));
                s1 = lo_(t) + hi_(t);
            }
            {
                const ulonglong2* q = reinterpret_cast<const ulonglong2*>(red2[wid]);
                ulonglong2 v0 = q[lane], v1 = q[lane + 32], v2 = q[lane + 64], v3 = q[lane + 96];
                ull t = fadd2(fadd2(fadd2(v0.x, v0.y), fadd2(v1.x, v1.y)),
                              fadd2(fadd2(v2.x, v2.y), fadd2(v3.x, v3.y)));
                s2 = lo_(t) + hi_(t);
            }
            #pragma unroll
            for (int off = 16; off > 0; off >>= 1) {
                s0 += __shfl_xor_sync(0xffffffffu, s0, off);
                s1 += __shfl_xor_sync(0xffffffffu, s1, off);
                s2 += __shfl_xor_sync(0xffffffffu, s2, off);
            }
            if (lane == 0) {
                const float MAXN = 1.0f - 1e-5f;
                const float EPSN = 1e-5f;
                float x2 = s0, y2 = s1, xy = s2;

                float nx = sqrtf(x2);
                float sx = (nx > MAXN) ? __fdividef(MAXN, fmaxf(nx, EPSN)) : 1.0f;
                float ny = sqrtf(y2);
                float sy = (ny > MAXN) ? __fdividef(MAXN, fmaxf(ny, EPSN)) : 1.0f;

                float X2 = sx * sx * x2;
                float Y2 = sy * sy * y2;
                float XY = sx * sy * xy;

                float A_  = 1.0f + 2.0f * XY + Y2;
                float B_  = 1.0f - X2;
                float den = fmaxf(1.0f + 2.0f * XY + X2 * Y2, 1e-15f);

                float n2 = (A_ * A_ * X2 + 2.0f * A_ * B_ * XY + B_ * B_ * Y2)
                           / (den * den);
                float no = sqrtf(fmaxf(n2, 0.0f));
                float sf = (no > MAXN) ? __fdividef(MAXN, fmaxf(no, EPSN)) : 1.0f;

                scx[wid] = dup_(__fdividef(sf * A_ * sx, den));
                scy[wid] = dup_(__fdividef(sf * B_ * sy, den));
            }
        }
        __syncthreads();

        // ---- store batch k, rotate ----
        const long long row0 = (long long)(b0 + k * S) * NB;
        #pragma unroll
        for (int row = 0; row < NB; ++row) {
            long long g = row0 + row;
            if (g < n_rows) {
                ull o = ffma2(scx[row], xc[row], fmul2(scy[row], dv[row]));
                __stcs(reinterpret_cast<ull*>(out + (size_t)g * D_ + d0), o);
            }
        }
        #pragma unroll
        for (int row = 0; row < NB; ++row) xc[row] = xn[row];
    }
}

extern "C" void kernel_launch(void* const* d_in, const int* in_sizes, int n_in,
                              void* d_out, int out_size)
{
    const int*   indices = (const int*)  d_in[0];
    const float* baseW   = (const float*)d_in[1];
    const float* loraA   = (const float*)d_in[2];
    const float* loraB   = (const float*)d_in[3];
    float*       out     = (float*)d_out;

    int n_rows = in_sizes[0];                    // 32768
    int nbatch = (n_rows + NB - 1) / NB;         // 16384
    int grid   = nbatch < 2 * 148 ? nbatch : 2 * 148;   // 2 CTAs per SM

    rlora_kernel<<<grid, TPB>>>(indices, baseW, loraA, loraB, out, n_rows, nbatch);
}